// round 2
// baseline (speedup 1.0000x reference)
#include <cuda_runtime.h>

// Fused DepthwiseSeparableConv3d: depthwise 3x3x3 (SAME) + bias + BN + ReLU,
// then pointwise 64->128 GEMM + bias + BN + ReLU.
// B=2, D=H=W=48, C=64, F=128. fp32, packed f32x2 FMA in the GEMM.
// R2: block covers 2 h-rows (96 w). GEMM uses warp-uniform f-tile (broadcast
// weight LDS) + per-lane w (conflict-free y LDS), f-pair f32x2 accumulators.

#define NB   2
#define ND   48
#define NC   64
#define NF   128
#define SYS  97   // sY row stride (odd -> conflict-free stage-1 stores)

__device__ __forceinline__ unsigned long long dup2(float v) {
    unsigned long long r;
    unsigned u = __float_as_uint(v);
    asm("mov.b64 %0, {%1, %1};" : "=l"(r) : "r"(u));
    return r;
}

__device__ __forceinline__ void fma2(unsigned long long& d,
                                     unsigned long long a,
                                     unsigned long long b) {
    asm("fma.rn.f32x2 %0, %1, %2, %0;" : "+l"(d) : "l"(a), "l"(b));
}

__global__ __launch_bounds__(256, 2)
void dwsep3d_fused_kernel(
    const float* __restrict__ x,
    const float* __restrict__ dwk,   // (3,3,3,1,C)
    const float* __restrict__ dwb,   // (C)
    const float* __restrict__ g1, const float* __restrict__ b1,
    const float* __restrict__ m1, const float* __restrict__ v1,
    const float* __restrict__ pw,    // (C,F)
    const float* __restrict__ pb,    // (F)
    const float* __restrict__ g2, const float* __restrict__ b2,
    const float* __restrict__ m2, const float* __restrict__ v2,
    float* __restrict__ out)
{
    __shared__ float sW[NC * NF];      // 32768 B, pointwise weights [c][f]
    __shared__ float sY[NC * SYS];     // 24832 B, stage-1 result [c][widx 0..95]
    __shared__ float sS1[NC], sT1[NC];
    __shared__ float sS2[NF], sT2[NF];

    const int tid = threadIdx.x;
    const int bid = blockIdx.x;            // 0 .. B*D*24-1
    const int h0 = (bid % 24) * 2;         // pair of h rows
    const int d  = (bid / 24) % ND;
    const int b  = bid / (24 * ND);

    // ---- stage 0: stage pointwise weights + fold BN params -------------------
    {
        const float4* src = (const float4*)pw;
        float4* dst = (float4*)sW;
        #pragma unroll
        for (int i = tid; i < NC * NF / 4; i += 256) dst[i] = src[i];
    }
    if (tid < NC) {
        const int c = tid;
        float inv = g1[c] * rsqrtf(v1[c] + 1e-3f);
        sS1[c] = inv;
        sT1[c] = dwb[c] * inv + b1[c] - m1[c] * inv;   // folds dw bias + BN1
    } else if (tid < NC + NF) {
        const int f = tid - NC;
        float inv = g2[f] * rsqrtf(v2[f] + 1e-3f);
        sS2[f] = inv;
        sT2[f] = pb[f] * inv + b2[f] - m2[f] * inv;    // folds pw bias + BN2
    }
    __syncthreads();

    // ---- stage 1: depthwise 3x3x3 + BN1 + ReLU -> sY[c][widx] ----------------
    {
        const int c  = tid & 63;           // channel
        const int wg = tid >> 6;           // 0..3 -> w range [wg*12, wg*12+12)
        const int w0 = wg * 12;
        const float s1v = sS1[c], t1v = sT1[c];

        #pragma unroll
        for (int hr = 0; hr < 2; hr++) {
            const int h = h0 + hr;
            float acc[12];
            #pragma unroll
            for (int j = 0; j < 12; j++) acc[j] = 0.f;

            #pragma unroll
            for (int dd = 0; dd < 3; dd++) {
                const int zd = d + dd - 1;
                if (zd < 0 || zd >= ND) continue;
                #pragma unroll
                for (int hh = 0; hh < 3; hh++) {
                    const int zh = h + hh - 1;
                    if (zh < 0 || zh >= ND) continue;
                    const float* xb =
                        x + (((size_t)((b * ND + zd) * ND + zh)) * ND) * NC + c;
                    float xv[14];
                    #pragma unroll
                    for (int j = 0; j < 14; j++) {
                        const int wx = w0 - 1 + j;
                        xv[j] = (wx >= 0 && wx < ND) ? __ldg(xb + wx * NC) : 0.f;
                    }
                    const int kb = ((dd * 3 + hh) * 3) * NC + c;
                    const float k0 = __ldg(dwk + kb);
                    const float k1 = __ldg(dwk + kb + NC);
                    const float k2 = __ldg(dwk + kb + 2 * NC);
                    #pragma unroll
                    for (int j = 0; j < 12; j++)
                        acc[j] = fmaf(xv[j], k0,
                                  fmaf(xv[j + 1], k1,
                                   fmaf(xv[j + 2], k2, acc[j])));
                }
            }
            #pragma unroll
            for (int j = 0; j < 12; j++)
                sY[c * SYS + hr * 48 + w0 + j] =
                    fmaxf(fmaf(acc[j], s1v, t1v), 0.f);
        }
    }
    __syncthreads();

    // ---- stage 2: GEMM z[96][128] = y[96][64] @ W[64][128] -------------------
    // warp: f-tile of 16 (uniform -> broadcast weight LDS); lane: w = lane+32p.
    {
        const int lane = tid & 31;
        const int wid  = tid >> 5;         // 0..7
        const int f0   = wid * 16;

        unsigned long long acc[3][8];      // [p][f-pair], pair = (f0+2q, f0+2q+1)
        #pragma unroll
        for (int p = 0; p < 3; p++)
            #pragma unroll
            for (int q = 0; q < 8; q++) acc[p][q] = 0ull;

        #pragma unroll 4
        for (int c = 0; c < NC; c++) {
            const ulonglong2* wp = (const ulonglong2*)&sW[c * NF + f0];
            const ulonglong2 wA = wp[0];   // f-pairs q=0,1
            const ulonglong2 wB = wp[1];   // q=2,3
            const ulonglong2 wC = wp[2];   // q=4,5
            const ulonglong2 wD = wp[3];   // q=6,7
            const float* yr = &sY[c * SYS + lane];
            const unsigned long long y0 = dup2(yr[0]);
            const unsigned long long y1 = dup2(yr[32]);
            const unsigned long long y2 = dup2(yr[64]);

            fma2(acc[0][0], y0, wA.x); fma2(acc[0][1], y0, wA.y);
            fma2(acc[0][2], y0, wB.x); fma2(acc[0][3], y0, wB.y);
            fma2(acc[0][4], y0, wC.x); fma2(acc[0][5], y0, wC.y);
            fma2(acc[0][6], y0, wD.x); fma2(acc[0][7], y0, wD.y);
            fma2(acc[1][0], y1, wA.x); fma2(acc[1][1], y1, wA.y);
            fma2(acc[1][2], y1, wB.x); fma2(acc[1][3], y1, wB.y);
            fma2(acc[1][4], y1, wC.x); fma2(acc[1][5], y1, wC.y);
            fma2(acc[1][6], y1, wD.x); fma2(acc[1][7], y1, wD.y);
            fma2(acc[2][0], y2, wA.x); fma2(acc[2][1], y2, wA.y);
            fma2(acc[2][2], y2, wB.x); fma2(acc[2][3], y2, wB.y);
            fma2(acc[2][4], y2, wC.x); fma2(acc[2][5], y2, wC.y);
            fma2(acc[2][6], y2, wD.x); fma2(acc[2][7], y2, wD.y);
        }

        // epilogue: BN2 + ReLU, float4 stores (16 f per lane-w)
        float s2[16], t2[16];
        #pragma unroll
        for (int q = 0; q < 4; q++) {
            *(float4*)&s2[q * 4] = *(const float4*)&sS2[f0 + q * 4];
            *(float4*)&t2[q * 4] = *(const float4*)&sT2[f0 + q * 4];
        }
        float* ob = out + (((size_t)((b * ND + d) * ND + h0)) * ND) * NF + f0;

        #pragma unroll
        for (int p = 0; p < 3; p++) {
            float z[16];
            #pragma unroll
            for (int q = 0; q < 8; q++) {
                const float lo = __uint_as_float((unsigned)(acc[p][q] & 0xffffffffull));
                const float hi = __uint_as_float((unsigned)(acc[p][q] >> 32));
                z[2 * q]     = fmaxf(fmaf(lo, s2[2 * q],     t2[2 * q]),     0.f);
                z[2 * q + 1] = fmaxf(fmaf(hi, s2[2 * q + 1], t2[2 * q + 1]), 0.f);
            }
            float* op = ob + (size_t)(lane + 32 * p) * NF;
            #pragma unroll
            for (int q = 0; q < 4; q++)
                *(float4*)&op[q * 4] = *(float4*)&z[q * 4];
        }
    }
}

extern "C" void kernel_launch(void* const* d_in, const int* in_sizes, int n_in,
                              void* d_out, int out_size) {
    const float* x   = (const float*)d_in[0];
    const float* dwk = (const float*)d_in[1];
    const float* dwb = (const float*)d_in[2];
    const float* g1  = (const float*)d_in[3];
    const float* b1  = (const float*)d_in[4];
    const float* m1  = (const float*)d_in[5];
    const float* v1  = (const float*)d_in[6];
    const float* pw  = (const float*)d_in[7];
    const float* pb  = (const float*)d_in[8];
    const float* g2  = (const float*)d_in[9];
    const float* b2  = (const float*)d_in[10];
    const float* m2  = (const float*)d_in[11];
    const float* v2  = (const float*)d_in[12];
    float* out = (float*)d_out;

    dim3 grid(NB * ND * 24);   // 2304 blocks: one (b,d,h-pair) -> 96 w each
    dim3 block(256);
    dwsep3d_fused_kernel<<<grid, block>>>(x, dwk, dwb, g1, b1, m1, v1,
                                          pw, pb, g2, b2, m2, v2, out);
}